// round 1
// baseline (speedup 1.0000x reference)
#include <cuda_runtime.h>
#include <math.h>

#define Bb   4
#define Nseq 2048
#define DIN  256
#define DM   512
#define Hh   8
#define DH   64
#define KTOP 32
#define MROWS (Bb*Nseq)   // 8192

// ---------------- scratch (device globals; no allocation allowed) ----------------
__device__ float g_Q[(size_t)Bb*Hh*Nseq*DH];
__device__ float g_K[(size_t)Bb*Hh*Nseq*DH];
__device__ float g_V[(size_t)Bb*Hh*Nseq*DH];
__device__ float g_O[(size_t)MROWS*DM];
__device__ int   g_tidx[(size_t)MROWS*KTOP];
__device__ float g_tval[(size_t)MROWS*KTOP];

// ---------------- generic 64x64-tile fp32 GEMM: C = A(MxK) * B(KxN) + bias ------
// mode 0: write head-split layout  out[((b*H+h)*N + n)*DH + d],  col = h*64+d, row m = b*N+n
// mode 1: plain row-major C[m*DM + col]
__global__ __launch_bounds__(256)
void gemm64(const float* __restrict__ A, int lda,
            const float* __restrict__ Bw, int ldb,
            const float* __restrict__ bias,
            float* __restrict__ C,
            int K, int mode)
{
    __shared__ float As[32*68];   // transposed: As[k][m]
    __shared__ float Bs[32*68];   // natural:    Bs[k][n]
    const int tid = threadIdx.x;
    const int tx = tid & 15, ty = tid >> 4;
    const int m0 = blockIdx.y * 64;
    const int n0 = blockIdx.x * 64;

    float acc[4][4];
#pragma unroll
    for (int i = 0; i < 4; i++)
#pragma unroll
        for (int j = 0; j < 4; j++) acc[i][j] = 0.f;

    for (int k0 = 0; k0 < K; k0 += 32) {
        // A tile 64x32, store transposed
#pragma unroll
        for (int rep = 0; rep < 2; rep++) {
            int lin = rep*256 + tid;        // 0..511
            int mr  = lin >> 3;             // 0..63
            int kq  = (lin & 7) << 2;       // 0..28
            float4 a = *(const float4*)(A + (size_t)(m0+mr)*lda + k0 + kq);
            As[(kq+0)*68 + mr] = a.x;
            As[(kq+1)*68 + mr] = a.y;
            As[(kq+2)*68 + mr] = a.z;
            As[(kq+3)*68 + mr] = a.w;
        }
        // B tile 32x64
#pragma unroll
        for (int rep = 0; rep < 2; rep++) {
            int lin = rep*256 + tid;
            int kk  = lin >> 4;             // 0..31
            int nn  = (lin & 15) << 2;
            *(float4*)&Bs[kk*68 + nn] =
                *(const float4*)(Bw + (size_t)(k0+kk)*ldb + n0 + nn);
        }
        __syncthreads();
#pragma unroll 8
        for (int kk = 0; kk < 32; kk++) {
            float4 av = *(const float4*)&As[kk*68 + 4*ty];
            float4 bv = *(const float4*)&Bs[kk*68 + 4*tx];
            float aa[4] = {av.x, av.y, av.z, av.w};
            float bb[4] = {bv.x, bv.y, bv.z, bv.w};
#pragma unroll
            for (int i = 0; i < 4; i++)
#pragma unroll
                for (int j = 0; j < 4; j++)
                    acc[i][j] = fmaf(aa[i], bb[j], acc[i][j]);
        }
        __syncthreads();
    }

    const int cg0 = n0 + 4*tx;
    const float bz0 = bias[cg0+0], bz1 = bias[cg0+1],
                bz2 = bias[cg0+2], bz3 = bias[cg0+3];
#pragma unroll
    for (int i = 0; i < 4; i++) {
        int m = m0 + 4*ty + i;
        float4 o = make_float4(acc[i][0]+bz0, acc[i][1]+bz1,
                               acc[i][2]+bz2, acc[i][3]+bz3);
        if (mode == 0) {
            int bi = m >> 11;            // m / N
            int nn = m & (Nseq-1);
            int h  = cg0 >> 6;
            int d  = cg0 & 63;
            size_t idx = (((size_t)(bi*Hh + h))*Nseq + nn)*DH + d;
            *(float4*)(C + idx) = o;
        } else {
            *(float4*)(C + (size_t)m*DM + cg0) = o;
        }
    }
}

// ---------------- top-k of similarity rows (jax tie-break: lower index wins) ----
__global__ __launch_bounds__(256)
void topk_kernel(const float* __restrict__ sim)
{
    __shared__ float s[Nseq];
    __shared__ float rv[8];
    __shared__ int   ri[8];
    __shared__ float wv[KTOP];
    __shared__ int   wi[KTOP];
    __shared__ float rsum_s;

    const int row  = blockIdx.x;            // 0..8191
    const int diag = row & (Nseq-1);
    const float* sr = sim + (size_t)row*Nseq;
    const int tid = threadIdx.x;
    const int lane = tid & 31, wid = tid >> 5;

    for (int j = tid; j < Nseq; j += 256) {
        float v = sr[j];
        s[j] = (j == diag) ? -1.0f : fmaxf(v, 0.0f);
    }
    __syncthreads();

    for (int it = 0; it < KTOP; it++) {
        float bv = -2.0f; int bi = 0x7fffffff;
#pragma unroll
        for (int j = tid; j < Nseq; j += 256) {
            float v = s[j];
            if (v > bv || (v == bv && j < bi)) { bv = v; bi = j; }
        }
#pragma unroll
        for (int mask = 16; mask > 0; mask >>= 1) {
            float ov = __shfl_xor_sync(0xffffffffu, bv, mask);
            int   oi = __shfl_xor_sync(0xffffffffu, bi, mask);
            if (ov > bv || (ov == bv && oi < bi)) { bv = ov; bi = oi; }
        }
        if (lane == 0) { rv[wid] = bv; ri[wid] = bi; }
        __syncthreads();
        if (tid == 0) {
            float fv = rv[0]; int fi = ri[0];
#pragma unroll
            for (int w = 1; w < 8; w++)
                if (rv[w] > fv || (rv[w] == fv && ri[w] < fi)) { fv = rv[w]; fi = ri[w]; }
            wv[it] = fv; wi[it] = fi;
            s[fi] = -1.0f;                 // remove winner
        }
        __syncthreads();
    }

    if (tid == 0) {
        float sum = 0.f;
        for (int e = 0; e < KTOP; e++) sum += wv[e];
        rsum_s = 1.0f / fmaxf(sum, 1e-8f);
    }
    __syncthreads();
    if (tid < KTOP) {
        g_tidx[(size_t)row*KTOP + tid] = wi[tid];
        g_tval[(size_t)row*KTOP + tid] = wv[tid] * rsum_s;
    }
}

// ---------------- flash attention with sparse top-k bias ------------------------
// grid: (N/64 q-tiles, B*H), 256 threads. Online softmax, 64x64 tiles.
#define SM_QT (64*68)
#define SM_KS (64*68)
#define SM_VS (64*68)
#define SM_SS (64*66)
#define SMEM_BYTES ((SM_QT+SM_KS+SM_VS+SM_SS)*4)

__global__ __launch_bounds__(256)
void attn_kernel(const float* __restrict__ tau_raw)
{
    extern __shared__ float smf[];
    float* Qt = smf;                 // Qt[d][r]  (transposed, scaled)
    float* Ks = Qt + SM_QT;          // Ks[d][c]  (transposed)
    float* Vs = Ks + SM_KS;          // Vs[c][d]  (natural)
    float* Ss = Vs + SM_VS;          // Ss[r][c]  stride 66

    const int tid = threadIdx.x;
    const int tx = tid & 15, ty = tid >> 4;
    const int z  = blockIdx.y;            // b*H + h
    const int bi = z >> 3;
    const int h  = z & 7;
    const int q0 = blockIdx.x * 64;
    const size_t base = (size_t)z * Nseq * DH;
    const float* Qg = g_Q + base;
    const float* Kg = g_K + base;
    const float* Vg = g_V + base;

    float tr  = tau_raw[0];
    float tau = (tr > 20.0f) ? tr : log1pf(__expf(tr));
    const float scale = 0.125f;            // 1/sqrt(64)

    // load Q tile (transposed + pre-scaled)
#pragma unroll
    for (int rep = 0; rep < 4; rep++) {
        int lin = rep*256 + tid;
        int r = lin >> 4;
        int d0 = (lin & 15) << 2;
        float4 qv = *(const float4*)(Qg + (size_t)(q0+r)*DH + d0);
        Qt[(d0+0)*68 + r] = qv.x*scale;
        Qt[(d0+1)*68 + r] = qv.y*scale;
        Qt[(d0+2)*68 + r] = qv.z*scale;
        Qt[(d0+3)*68 + r] = qv.w*scale;
    }

    float m_[4], l_[4], o_[4][4];
#pragma unroll
    for (int i = 0; i < 4; i++) {
        m_[i] = -INFINITY; l_[i] = 0.f;
#pragma unroll
        for (int j = 0; j < 4; j++) o_[i][j] = 0.f;
    }

    // bias scatter mapping (fixed per thread)
    const int srow  = tid >> 2;            // 0..63
    const int slane = tid & 3;
    const size_t brow = ((size_t)bi*Nseq + q0 + srow) * KTOP;

    for (int t = 0; t < Nseq/64; t++) {
        const int kb = t*64;
        __syncthreads();                    // protect smem reuse
        // load K (transposed) + V (natural)
#pragma unroll
        for (int rep = 0; rep < 4; rep++) {
            int lin = rep*256 + tid;
            int r = lin >> 4;
            int d0 = (lin & 15) << 2;
            float4 kv = *(const float4*)(Kg + (size_t)(kb+r)*DH + d0);
            Ks[(d0+0)*68 + r] = kv.x;
            Ks[(d0+1)*68 + r] = kv.y;
            Ks[(d0+2)*68 + r] = kv.z;
            Ks[(d0+3)*68 + r] = kv.w;
            float4 vv = *(const float4*)(Vg + (size_t)(kb+r)*DH + d0);
            *(float4*)&Vs[r*68 + d0] = vv;
        }
        __syncthreads();

        // S = (Q*scale) K^T
        float s[4][4];
#pragma unroll
        for (int i = 0; i < 4; i++)
#pragma unroll
            for (int j = 0; j < 4; j++) s[i][j] = 0.f;
#pragma unroll 4
        for (int kk = 0; kk < 64; kk++) {
            float4 qv = *(const float4*)&Qt[kk*68 + 4*ty];
            float4 kv = *(const float4*)&Ks[kk*68 + 4*tx];
            float aa[4] = {qv.x, qv.y, qv.z, qv.w};
            float bb[4] = {kv.x, kv.y, kv.z, kv.w};
#pragma unroll
            for (int i = 0; i < 4; i++)
#pragma unroll
                for (int j = 0; j < 4; j++)
                    s[i][j] = fmaf(aa[i], bb[j], s[i][j]);
        }
        // stage S to smem
#pragma unroll
        for (int i = 0; i < 4; i++) {
            *(float2*)&Ss[(4*ty+i)*66 + 4*tx]     = make_float2(s[i][0], s[i][1]);
            *(float2*)&Ss[(4*ty+i)*66 + 4*tx + 2] = make_float2(s[i][2], s[i][3]);
        }
        __syncthreads();

        // sparse bias scatter: 4 threads per row, 8 entries each
#pragma unroll
        for (int e = slane; e < KTOP; e += 4) {
            int gi = g_tidx[brow + e];
            unsigned off = (unsigned)(gi - kb);
            if (off < 64u)
                Ss[srow*66 + off] += tau * g_tval[brow + e];
        }
        __syncthreads();

        // online softmax update
#pragma unroll
        for (int i = 0; i < 4; i++) {
            float2 a0 = *(const float2*)&Ss[(4*ty+i)*66 + 4*tx];
            float2 a1 = *(const float2*)&Ss[(4*ty+i)*66 + 4*tx + 2];
            float sv[4] = {a0.x, a0.y, a1.x, a1.y};
            float mx = fmaxf(fmaxf(sv[0], sv[1]), fmaxf(sv[2], sv[3]));
#pragma unroll
            for (int mask = 8; mask > 0; mask >>= 1)
                mx = fmaxf(mx, __shfl_xor_sync(0xffffffffu, mx, mask));
            float mn = fmaxf(m_[i], mx);
            float alpha = __expf(m_[i] - mn);
            m_[i] = mn;
            l_[i] *= alpha;
#pragma unroll
            for (int j = 0; j < 4; j++) o_[i][j] *= alpha;
            float rs = 0.f;
#pragma unroll
            for (int j = 0; j < 4; j++) {
                float p = __expf(sv[j] - mn);
                sv[j] = p; rs += p;
            }
#pragma unroll
            for (int mask = 8; mask > 0; mask >>= 1)
                rs += __shfl_xor_sync(0xffffffffu, rs, mask);
            l_[i] += rs;
            *(float2*)&Ss[(4*ty+i)*66 + 4*tx]     = make_float2(sv[0], sv[1]);
            *(float2*)&Ss[(4*ty+i)*66 + 4*tx + 2] = make_float2(sv[2], sv[3]);
        }
        __syncthreads();

        // O += P V
#pragma unroll 2
        for (int kk = 0; kk < 64; kk++) {
            float4 vv = *(const float4*)&Vs[kk*68 + 4*tx];
            float p0 = Ss[(4*ty+0)*66 + kk];
            float p1 = Ss[(4*ty+1)*66 + kk];
            float p2 = Ss[(4*ty+2)*66 + kk];
            float p3 = Ss[(4*ty+3)*66 + kk];
            float vv_[4] = {vv.x, vv.y, vv.z, vv.w};
#pragma unroll
            for (int j = 0; j < 4; j++) {
                o_[0][j] = fmaf(p0, vv_[j], o_[0][j]);
                o_[1][j] = fmaf(p1, vv_[j], o_[1][j]);
                o_[2][j] = fmaf(p2, vv_[j], o_[2][j]);
                o_[3][j] = fmaf(p3, vv_[j], o_[3][j]);
            }
        }
    }

    // epilogue: O /= l, write head-merged layout (b, n, h*64+d)
#pragma unroll
    for (int i = 0; i < 4; i++) {
        float inv = 1.0f / l_[i];
        float4 ov = make_float4(o_[i][0]*inv, o_[i][1]*inv,
                                o_[i][2]*inv, o_[i][3]*inv);
        int q = q0 + 4*ty + i;
        size_t idx = ((size_t)bi*Nseq + q)*DM + h*DH + 4*tx;
        *(float4*)(g_O + idx) = ov;
    }
}

// ---------------- launch ---------------------------------------------------------
extern "C" void kernel_launch(void* const* d_in, const int* in_sizes, int n_in,
                              void* d_out, int out_size)
{
    const float* x   = (const float*)d_in[0];
    const float* sim = (const float*)d_in[1];
    const float* Wq  = (const float*)d_in[2];
    const float* bq  = (const float*)d_in[3];
    const float* Wk  = (const float*)d_in[4];
    const float* bk  = (const float*)d_in[5];
    const float* Wv  = (const float*)d_in[6];
    const float* bv  = (const float*)d_in[7];
    const float* Wo  = (const float*)d_in[8];
    const float* bo  = (const float*)d_in[9];
    const float* tau = (const float*)d_in[10];
    float* out = (float*)d_out;

    float *qp, *kp, *vp, *op;
    cudaGetSymbolAddress((void**)&qp, g_Q);
    cudaGetSymbolAddress((void**)&kp, g_K);
    cudaGetSymbolAddress((void**)&vp, g_V);
    cudaGetSymbolAddress((void**)&op, g_O);

    dim3 gq(DM/64, MROWS/64);   // (8, 128)

    gemm64<<<gq, 256>>>(x, DIN, Wq, DM, bq, qp, DIN, 0);
    gemm64<<<gq, 256>>>(x, DIN, Wk, DM, bk, kp, DIN, 0);
    gemm64<<<gq, 256>>>(x, DIN, Wv, DM, bv, vp, DIN, 0);

    topk_kernel<<<MROWS, 256>>>(sim);

    cudaFuncSetAttribute(attn_kernel,
                         cudaFuncAttributeMaxDynamicSharedMemorySize, SMEM_BYTES);
    attn_kernel<<<dim3(Nseq/64, Bb*Hh), 256, SMEM_BYTES>>>(tau);

    gemm64<<<gq, 256>>>(op, DM, Wo, DM, bo, out, DM, 1);
}